// round 4
// baseline (speedup 1.0000x reference)
#include <cuda_runtime.h>
#include <math.h>

#define Bb   2
#define Tt   512
#define Hh   16
#define BHT  16384

typedef unsigned long long u64;

// ---------------- scratch ----------------------------------------------------
__device__ float g_q [BHT*64];
__device__ float g_k [BHT*64];
__device__ float g_v [BHT*64];
__device__ float g_km[BHT*32];
__device__ float g_k2[BHT];
__device__ float g_U [BHT*128];
__device__ float g_m [BHT*32];
__device__ float g_c [BHT];
__device__ float g_pacc[2][BHT*64];
__device__ float g_psum[2][BHT];
__device__ float g_ao[Bb*Tt*1024];

// ---------------- f32x2 helpers ----------------------------------------------
__device__ __forceinline__ u64 pk2(float a, float b) {
    u64 r; asm("mov.b64 %0,{%1,%2};" : "=l"(r) : "f"(a), "f"(b)); return r;
}
__device__ __forceinline__ void fma2(u64 &d, u64 a, u64 b) {
    asm("fma.rn.f32x2 %0,%1,%2,%0;" : "+l"(d) : "l"(a), "l"(b));
}
__device__ __forceinline__ float2 up2(u64 a) {
    float2 r; asm("mov.b64 {%0,%1},%2;" : "=f"(r.x), "=f"(r.y) : "l"(a)); return r;
}

// ---------------- tf32 helpers ------------------------------------------------
__device__ __forceinline__ uint2 spl(float x) {
    unsigned h, l;
    asm("cvt.rna.tf32.f32 %0,%1;" : "=r"(h) : "f"(x));
    float hf = __uint_as_float(h);
    asm("cvt.rna.tf32.f32 %0,%1;" : "=r"(l) : "f"(x - hf));
    return make_uint2(h, l);
}
__device__ __forceinline__ void mma8(float* c,
    unsigned a0, unsigned a1, unsigned a2, unsigned a3,
    unsigned b0, unsigned b1)
{
    asm volatile(
        "mma.sync.aligned.m16n8k8.row.col.f32.tf32.tf32.f32 "
        "{%0,%1,%2,%3},{%4,%5,%6,%7},{%8,%9},{%0,%1,%2,%3};"
        : "+f"(c[0]), "+f"(c[1]), "+f"(c[2]), "+f"(c[3])
        : "r"(a0), "r"(a1), "r"(a2), "r"(a3), "r"(b0), "r"(b1));
}

// ---------------- GEMM via tensor cores (3xTF32) — unchanged from R3 ----------
#define SA_STR 36
#define SB_STR 68
#define GEMM_SMEM ((128*SA_STR + 32*SB_STR) * 8)

__global__ void __launch_bounds__(256) gemm_tc(
    const float* __restrict__ A,
    const float* __restrict__ W0, const float* __restrict__ W1,
    const float* __restrict__ W2,
    float* __restrict__ Cout, int mode)
{
    extern __shared__ uint2 sm2[];
    uint2* sA = sm2;
    uint2* sB = sm2 + 128 * SA_STR;

    const float* Ap = (mode == 0) ? A : g_ao;
    const float* Wm = (mode == 0)
        ? (blockIdx.z == 0 ? W0 : (blockIdx.z == 1 ? W1 : W2))
        : W0;

    int tid  = threadIdx.x;
    int lane = tid & 31;
    int wid  = tid >> 5;
    int wm   = wid & 3;
    int wn   = wid >> 2;
    int g    = lane >> 2;
    int tg   = lane & 3;
    int row0 = blockIdx.y * 128;
    int col0 = blockIdx.x * 64;

    int aRow[4], aC4[4], sAi[4];
    #pragma unroll
    for (int e = 0; e < 4; e++) {
        int idx = tid + e * 256;
        aRow[e] = idx >> 3; aC4[e] = idx & 7;
        sAi[e]  = aRow[e] * SA_STR + aC4[e] * 4;
    }
    int bRow[2], bC4[2], sBi[2];
    #pragma unroll
    for (int e = 0; e < 2; e++) {
        int idx = tid + e * 256;
        bRow[e] = idx >> 4; bC4[e] = idx & 15;
        sBi[e]  = bRow[e] * SB_STR + bC4[e] * 4;
    }

    float acc[2][4][4];
    #pragma unroll
    for (int mt = 0; mt < 2; mt++)
        #pragma unroll
        for (int nt = 0; nt < 4; nt++)
            #pragma unroll
            for (int e = 0; e < 4; e++) acc[mt][nt][e] = 0.f;

    float4 av[4], bv[2];
    #pragma unroll
    for (int e = 0; e < 4; e++)
        av[e] = *(const float4*)&Ap[(row0 + aRow[e]) * 1024 + aC4[e] * 4];
    #pragma unroll
    for (int e = 0; e < 2; e++)
        bv[e] = *(const float4*)&Wm[bRow[e] * 1024 + col0 + bC4[e] * 4];

    for (int t = 0; t < 32; t++) {
        __syncthreads();
        #pragma unroll
        for (int e = 0; e < 4; e++) {
            uint2* d = &sA[sAi[e]];
            d[0] = spl(av[e].x); d[1] = spl(av[e].y);
            d[2] = spl(av[e].z); d[3] = spl(av[e].w);
        }
        #pragma unroll
        for (int e = 0; e < 2; e++) {
            uint2* d = &sB[sBi[e]];
            d[0] = spl(bv[e].x); d[1] = spl(bv[e].y);
            d[2] = spl(bv[e].z); d[3] = spl(bv[e].w);
        }
        __syncthreads();

        if (t < 31) {
            int k0 = (t + 1) * 32;
            #pragma unroll
            for (int e = 0; e < 4; e++)
                av[e] = *(const float4*)&Ap[(row0 + aRow[e]) * 1024 + k0 + aC4[e] * 4];
            #pragma unroll
            for (int e = 0; e < 2; e++)
                bv[e] = *(const float4*)&Wm[(k0 + bRow[e]) * 1024 + col0 + bC4[e] * 4];
        }

        #pragma unroll
        for (int kk = 0; kk < 32; kk += 8) {
            uint2 Afr[2][4];
            #pragma unroll
            for (int mt = 0; mt < 2; mt++) {
                int rb = (wm * 32 + mt * 16 + g) * SA_STR + kk + tg;
                Afr[mt][0] = sA[rb];
                Afr[mt][2] = sA[rb + 4];
                Afr[mt][1] = sA[rb + 8 * SA_STR];
                Afr[mt][3] = sA[rb + 8 * SA_STR + 4];
            }
            #pragma unroll
            for (int nt = 0; nt < 4; nt++) {
                int cb = (kk + tg) * SB_STR + wn * 32 + nt * 8 + g;
                uint2 B0 = sB[cb];
                uint2 B1 = sB[cb + 4 * SB_STR];
                #pragma unroll
                for (int mt = 0; mt < 2; mt++) {
                    float* c = acc[mt][nt];
                    mma8(c, Afr[mt][0].x, Afr[mt][1].x, Afr[mt][2].x, Afr[mt][3].x,
                         B0.x, B1.x);
                    mma8(c, Afr[mt][0].x, Afr[mt][1].x, Afr[mt][2].x, Afr[mt][3].x,
                         B0.y, B1.y);
                    mma8(c, Afr[mt][0].y, Afr[mt][1].y, Afr[mt][2].y, Afr[mt][3].y,
                         B0.x, B1.x);
                }
            }
        }
    }

    if (mode == 1) {
        #pragma unroll
        for (int mt = 0; mt < 2; mt++) {
            int row = row0 + wm * 32 + mt * 16 + g;
            #pragma unroll
            for (int nt = 0; nt < 4; nt++) {
                int col = col0 + wn * 32 + nt * 8 + 2 * tg;
                *(float2*)&Cout[row * 1024 + col] =
                    make_float2(acc[mt][nt][0], acc[mt][nt][1]);
                *(float2*)&Cout[(row + 8) * 1024 + col] =
                    make_float2(acc[mt][nt][2], acc[mt][nt][3]);
            }
        }
    } else {
        int z = blockIdx.z;
        float* dst = (z == 0) ? g_q : (z == 1) ? g_k : g_v;
        int h = blockIdx.x;
        #pragma unroll
        for (int mt = 0; mt < 2; mt++) {
            int row = row0 + wm * 32 + mt * 16 + g;
            int b0r = row >> 9, t0r = row & 511;
            int b1r = (row + 8) >> 9, t1r = (row + 8) & 511;
            #pragma unroll
            for (int nt = 0; nt < 4; nt++) {
                int col = wn * 32 + nt * 8 + 2 * tg;
                *(float2*)&dst[(((b0r << 4) + h) * 512 + t0r) * 64 + col] =
                    make_float2(acc[mt][nt][0], acc[mt][nt][1]);
                *(float2*)&dst[(((b1r << 4) + h) * 512 + t1r) * 64 + col] =
                    make_float2(acc[mt][nt][2], acc[mt][nt][3]);
            }
        }
    }
}

// ---------------- RoPE (in place on g_q, g_k) -------------------------------
__global__ void rope_kernel()
{
    int idx = blockIdx.x * blockDim.x + threadIdx.x;
    if (idx >= BHT * 32) return;
    int tok = idx >> 5;
    int j   = idx & 31;
    int t   = tok & 511;
    float inv = expf(-((float)(2 * j) / 64.0f) * 9.210340371976184f);
    float fr  = (float)t * inv;
    float s, c;
    sincosf(fr, &s, &c);

    float* q = g_q + tok * 64;
    float x1 = q[j], x2 = q[j + 32];
    q[j]      = x1 * c - x2 * s;
    q[j + 32] = x1 * s + x2 * c;

    float* k = g_k + tok * 64;
    x1 = k[j]; x2 = k[j + 32];
    k[j]      = x1 * c - x2 * s;
    k[j + 32] = x1 * s + x2 * c;
}

// ---------------- metric (R2 variant): km, k2, U, m = qm+w, c = q2+|Uq|^2 ----
__global__ void __launch_bounds__(256) metric_kernel(
    const float* __restrict__ Wqm, const float* __restrict__ Wkm,
    const float* __restrict__ Wmetric)
{
    __shared__ float sWqm[64 * 32];
    __shared__ float sWkm[64 * 32];
    __shared__ float sWm [32 * 128];
    int tid = threadIdx.x;
    for (int i = tid; i < 64 * 32; i += 256) { sWqm[i] = Wqm[i]; sWkm[i] = Wkm[i]; }
    for (int i = tid; i < 32 * 128; i += 256) { sWm[i] = Wmetric[i]; }
    __syncthreads();

    const unsigned FULL = 0xffffffffu;
    int w = tid >> 5, lane = tid & 31;
    int tok = blockIdx.x * 8 + w;

    const float* q = g_q + tok * 64;
    const float* k = g_k + tok * 64;
    float a0 = q[lane], a1 = q[lane + 32];
    float b0 = k[lane], b1 = k[lane + 32];

    float accq = 0.f, acck = 0.f;
    #pragma unroll
    for (int d = 0; d < 32; d++) {
        float qd = __shfl_sync(FULL, a0, d);
        float kd = __shfl_sync(FULL, b0, d);
        accq += qd * sWqm[d * 32 + lane];
        acck += kd * sWkm[d * 32 + lane];
    }
    #pragma unroll
    for (int d = 0; d < 32; d++) {
        float qd = __shfl_sync(FULL, a1, d);
        float kd = __shfl_sync(FULL, b1, d);
        accq += qd * sWqm[(d + 32) * 32 + lane];
        acck += kd * sWkm[(d + 32) * 32 + lane];
    }
    float qmv = 1.f / (1.f + expf(-accq));
    float kmv = 1.f / (1.f + expf(-acck));
    g_km[tok * 32 + lane] = kmv;

    float q2 = qmv * qmv, k2 = kmv * kmv;
    #pragma unroll
    for (int o = 16; o > 0; o >>= 1) {
        q2 += __shfl_xor_sync(FULL, q2, o);
        k2 += __shfl_xor_sync(FULL, k2, o);
    }
    if (lane == 0) g_k2[tok] = k2;

    float u0 = 0.f, u1 = 0.f, u2 = 0.f, u3 = 0.f;
    #pragma unroll
    for (int d = 0; d < 32; d++) {
        float qd = __shfl_sync(FULL, qmv, d);
        float4 wv = *(const float4*)&sWm[d * 128 + lane * 4];
        u0 += qd * wv.x; u1 += qd * wv.y; u2 += qd * wv.z; u3 += qd * wv.w;
    }
    *(float4*)&g_U[tok * 128 + lane * 4] = make_float4(u0, u1, u2, u3);

    float p0 = u0 * qmv, p1 = u1 * qmv, p2 = u2 * qmv, p3 = u3 * qmv;
    #pragma unroll
    for (int o = 16; o > 0; o >>= 1) {
        p0 += __shfl_xor_sync(FULL, p0, o);
        p1 += __shfl_xor_sync(FULL, p1, o);
        p2 += __shfl_xor_sync(FULL, p2, o);
        p3 += __shfl_xor_sync(FULL, p3, o);
    }
    float wd = p0 * u0 + p1 * u1 + p2 * u2 + p3 * u3;
    g_m[tok * 32 + lane] = qmv + wd;
    if (lane == 0)
        g_c[tok] = q2 + p0 * p0 + p1 * p1 + p2 * p2 + p3 * p3;
}

// ---------------- attention v3 ------------------------------------------------
// dist(i,j) = c_i + k2_j - 2 m_i.km_j + sum_r (U_i.km_j)^2 ; p = exp(-dist/T)
// Two-phase, U/m staged in smem once per block, j-split partials.
#define SM_U   0                      // 64*132
#define SM_M   (64*132)               // 64*36
#define SM_KM  (SM_M + 64*36)         // 64*36
#define SM_V   (SM_KM + 64*36)        // 64*64
#define SM_P   (SM_V + 64*64)         // 64*68
#define SM_C   (SM_P + 64*68)         // 64
#define SM_K2  (SM_C + 64)            // 64
#define ATTN_SMEM ((SM_K2 + 64) * 4)

__global__ void __launch_bounds__(256, 2) attn3(const float* __restrict__ temp_ptr)
{
    extern __shared__ float sm[];
    float* sU  = sm + SM_U;
    float* sM  = sm + SM_M;
    float* sKm = sm + SM_KM;
    float* sV  = sm + SM_V;
    float* sP  = sm + SM_P;
    float* sC  = sm + SM_C;
    float* sK2 = sm + SM_K2;

    int pidx = 14 - blockIdx.x;           // heavy blocks first
    int qt, jc;
    if (pidx == 0) { qt = 0; jc = 0; }
    else { qt = (pidx + 1) >> 1; jc = (pidx + 1) & 1; }
    int bh = blockIdx.y;
    int tok0 = bh * 512 + qt * 64;
    int tid = threadIdx.x;
    float invT = 1.0f / fmaxf(temp_ptr[0], 0.5f);

    // ---- stage U, m, c for this block's 64 queries ----
    #pragma unroll
    for (int e = 0; e < 8; e++) {
        int idx = tid + e * 256;          // 2048 float4
        int r = idx >> 5, c4 = idx & 31;
        float4 v = *(const float4*)&g_U[(tok0 + r) * 128 + c4 * 4];
        *(float4*)&sU[r * 132 + c4 * 4] = v;
    }
    #pragma unroll
    for (int e = 0; e < 2; e++) {
        int idx = tid + e * 256;          // 512 float4
        int r = idx >> 3, c4 = idx & 7;
        float4 v = *(const float4*)&g_m[(tok0 + r) * 32 + c4 * 4];
        *(float4*)&sM[r * 36 + c4 * 4] = v;
    }
    if (tid < 64) sC[tid] = g_c[tok0 + tid];
    __syncthreads();

    // phase-A identity: warp-uniform j slice
    int iaA = tid & 63, jqA = tid >> 6;
    float4 mq[8];
    #pragma unroll
    for (int dd = 0; dd < 8; dd++) mq[dd] = *(const float4*)&sM[iaA * 36 + dd * 4];
    float ci = sC[iaA];
    const float* Urow = &sU[iaA * 132];

    // phase-B identity
    int iaB = tid >> 2, jqB = tid & 3;

    u64 vacc[8];
    #pragma unroll
    for (int e = 0; e < 8; e++) vacc[e] = 0ull;
    float sumP = 0.f;

    int ntile = ((qt - jc) >> 1) + 1;
    for (int s = 0; s < ntile; s++) {
        int jt = jc + 2 * s;
        int tokJ = bh * 512 + jt * 64;
        __syncthreads();
        #pragma unroll
        for (int e = 0; e < 2; e++) {
            int idx = tid + e * 256;
            int r = idx >> 3, c4 = idx & 7;
            float4 v = *(const float4*)&g_km[(tokJ + r) * 32 + c4 * 4];
            *(float4*)&sKm[r * 36 + c4 * 4] = v;
        }
        #pragma unroll
        for (int e = 0; e < 4; e++) {
            int idx = tid + e * 256;
            *(float4*)&sV[idx * 4] = *(const float4*)&g_v[tokJ * 64 + idx * 4];
        }
        if (tid < 64) sK2[tid] = g_k2[tokJ + tid];
        __syncthreads();

        // ---- phase A: scores ----
        bool diag = (jt == qt);
        #pragma unroll 4
        for (int jj = 0; jj < 16; jj++) {
            int j = jqA * 16 + jj;
            float qk = 0.f;
            u64 uk01 = 0ull, uk23 = 0ull;
            #pragma unroll
            for (int dd = 0; dd < 8; dd++) {
                float4 kv = *(const float4*)&sKm[j * 36 + dd * 4];
                float4 mv = mq[dd];
                qk += mv.x * kv.x + mv.y * kv.y + mv.z * kv.z + mv.w * kv.w;
                const float* ub = Urow + dd * 16;
                longlong2 U0 = *(const longlong2*)(ub);
                longlong2 U1 = *(const longlong2*)(ub + 4);
                longlong2 U2 = *(const longlong2*)(ub + 8);
                longlong2 U3 = *(const longlong2*)(ub + 12);
                u64 kx;
                kx = pk2(kv.x, kv.x); fma2(uk01, (u64)U0.x, kx); fma2(uk23, (u64)U0.y, kx);
                kx = pk2(kv.y, kv.y); fma2(uk01, (u64)U1.x, kx); fma2(uk23, (u64)U1.y, kx);
                kx = pk2(kv.z, kv.z); fma2(uk01, (u64)U2.x, kx); fma2(uk23, (u64)U2.y, kx);
                kx = pk2(kv.w, kv.w); fma2(uk01, (u64)U3.x, kx); fma2(uk23, (u64)U3.y, kx);
            }
            float2 a = up2(uk01), b = up2(uk23);
            float dist = ci + sK2[j] - 2.f * qk
                       + a.x * a.x + a.y * a.y + b.x * b.x + b.y * b.y;
            float p = __expf(-fmaxf(dist, 0.f) * invT);
            if (diag && j > iaA) p = 0.f;
            sP[iaA * 68 + j] = p;
        }
        __syncthreads();

        // ---- phase B: vacc += P @ V ----
        const float* Vc = sV + jqB * 16;
        const float* Pr = sP + iaB * 68;
        #pragma unroll 4
        for (int j = 0; j < 64; j++) {
            float p = Pr[j];
            sumP += p;
            u64 pp = pk2(p, p);
            const float* vr = Vc + j * 64;
            longlong2 v0 = *(const longlong2*)(vr);
            longlong2 v1 = *(const longlong2*)(vr + 4);
            longlong2 v2 = *(const longlong2*)(vr + 8);
            longlong2 v3 = *(const longlong2*)(vr + 12);
            fma2(vacc[0], pp, (u64)v0.x); fma2(vacc[1], pp, (u64)v0.y);
            fma2(vacc[2], pp, (u64)v1.x); fma2(vacc[3], pp, (u64)v1.y);
            fma2(vacc[4], pp, (u64)v2.x); fma2(vacc[5], pp, (u64)v2.y);
            fma2(vacc[6], pp, (u64)v3.x); fma2(vacc[7], pp, (u64)v3.y);
        }
    }

    // ---- write partials ----
    if (jqB == 0) g_psum[jc][tok0 + iaB] = sumP;
    float* dst = &g_pacc[jc][(tok0 + iaB) * 64 + jqB * 16];
    #pragma unroll
    for (int e = 0; e < 4; e++) {
        float2 f0 = up2(vacc[2 * e]);
        float2 f1 = up2(vacc[2 * e + 1]);
        *(float4*)&dst[e * 4] = make_float4(f0.x, f0.y, f1.x, f1.y);
    }
}

// ---------------- merge partials -> g_ao -------------------------------------
__global__ void merge_kernel()
{
    int idx = blockIdx.x * 256 + threadIdx.x;    // 262144 items
    int tok = idx >> 4, c4 = idx & 15;
    int i = tok & 511;
    float4 a = *(const float4*)&g_pacc[0][tok * 64 + c4 * 4];
    float s = g_psum[0][tok];
    if (i >= 64) {
        float4 b = *(const float4*)&g_pacc[1][tok * 64 + c4 * 4];
        a.x += b.x; a.y += b.y; a.z += b.z; a.w += b.w;
        s += g_psum[1][tok];
    }
    float inv = 1.f / s;
    int bh = tok >> 9;
    int b = bh >> 4, h = bh & 15;
    float4 o = make_float4(a.x * inv, a.y * inv, a.z * inv, a.w * inv);
    *(float4*)&g_ao[(b * 512 + i) * 1024 + h * 64 + c4 * 4] = o;
}

// ---------------- launch ------------------------------------------------------
extern "C" void kernel_launch(void* const* d_in, const int* in_sizes, int n_in,
                              void* d_out, int out_size)
{
    const float* x    = (const float*)d_in[0];
    const float* Wq   = (const float*)d_in[1];
    const float* Wk   = (const float*)d_in[2];
    const float* Wv   = (const float*)d_in[3];
    const float* Wo   = (const float*)d_in[4];
    const float* Wqm  = (const float*)d_in[5];
    const float* Wkm  = (const float*)d_in[6];
    const float* Wmet = (const float*)d_in[7];
    const float* temp = (const float*)d_in[8];
    float*       out  = (float*)d_out;

    cudaFuncSetAttribute(gemm_tc,
                         cudaFuncAttributeMaxDynamicSharedMemorySize, GEMM_SMEM);
    cudaFuncSetAttribute(attn3,
                         cudaFuncAttributeMaxDynamicSharedMemorySize, ATTN_SMEM);

    gemm_tc<<<dim3(16, 8, 3), 256, GEMM_SMEM>>>(x, Wq, Wk, Wv, nullptr, 0);
    rope_kernel<<<(BHT * 32) / 256, 256>>>();
    metric_kernel<<<BHT / 8, 256>>>(Wqm, Wkm, Wmet);
    attn3<<<dim3(15, 32), 256, ATTN_SMEM>>>(temp);
    merge_kernel<<<1024, 256>>>();
    gemm_tc<<<dim3(16, 8, 1), 256, GEMM_SMEM>>>(nullptr, Wo, nullptr, nullptr, out, 1);
}

// round 5
// speedup vs baseline: 1.4273x; 1.4273x over previous
#include <cuda_runtime.h>
#include <math.h>

#define Bb   2
#define Tt   512
#define Hh   16
#define BHT  16384

#define TQ 128
#define TJ 64
#define USTRIDE 132

// ---------------- scratch ----------------------------------------------------
__device__ float g_q [BHT*64];
__device__ float g_k [BHT*64];
__device__ float g_v [BHT*64];
__device__ float g_qm[BHT*32];
__device__ float g_km[BHT*32];
__device__ float g_q2[BHT];
__device__ float g_k2[BHT];
__device__ float g_U [BHT*128];
__device__ float g_Uq[BHT*4];
__device__ float g_pacc[2][BHT*64];
__device__ float g_psum[2][BHT];
__device__ float g_ao[Bb*Tt*1024];

// ---------------- tf32 helpers ------------------------------------------------
__device__ __forceinline__ uint2 spl(float x) {
    unsigned h, l;
    asm("cvt.rna.tf32.f32 %0,%1;" : "=r"(h) : "f"(x));
    float hf = __uint_as_float(h);
    asm("cvt.rna.tf32.f32 %0,%1;" : "=r"(l) : "f"(x - hf));
    return make_uint2(h, l);
}
__device__ __forceinline__ void mma8(float* c,
    unsigned a0, unsigned a1, unsigned a2, unsigned a3,
    unsigned b0, unsigned b1)
{
    asm volatile(
        "mma.sync.aligned.m16n8k8.row.col.f32.tf32.tf32.f32 "
        "{%0,%1,%2,%3},{%4,%5,%6,%7},{%8,%9},{%0,%1,%2,%3};"
        : "+f"(c[0]), "+f"(c[1]), "+f"(c[2]), "+f"(c[3])
        : "r"(a0), "r"(a1), "r"(a2), "r"(a3), "r"(b0), "r"(b1));
}

// ---------------- GEMM via tensor cores (3xTF32) — unchanged from R3 ----------
#define SA_STR 36
#define SB_STR 68
#define GEMM_SMEM ((128*SA_STR + 32*SB_STR) * 8)

__global__ void __launch_bounds__(256) gemm_tc(
    const float* __restrict__ A,
    const float* __restrict__ W0, const float* __restrict__ W1,
    const float* __restrict__ W2,
    float* __restrict__ Cout, int mode)
{
    extern __shared__ uint2 sm2[];
    uint2* sA = sm2;
    uint2* sB = sm2 + 128 * SA_STR;

    const float* Ap = (mode == 0) ? A : g_ao;
    const float* Wm = (mode == 0)
        ? (blockIdx.z == 0 ? W0 : (blockIdx.z == 1 ? W1 : W2))
        : W0;

    int tid  = threadIdx.x;
    int lane = tid & 31;
    int wid  = tid >> 5;
    int wm   = wid & 3;
    int wn   = wid >> 2;
    int g    = lane >> 2;
    int tg   = lane & 3;
    int row0 = blockIdx.y * 128;
    int col0 = blockIdx.x * 64;

    int aRow[4], aC4[4], sAi[4];
    #pragma unroll
    for (int e = 0; e < 4; e++) {
        int idx = tid + e * 256;
        aRow[e] = idx >> 3; aC4[e] = idx & 7;
        sAi[e]  = aRow[e] * SA_STR + aC4[e] * 4;
    }
    int bRow[2], bC4[2], sBi[2];
    #pragma unroll
    for (int e = 0; e < 2; e++) {
        int idx = tid + e * 256;
        bRow[e] = idx >> 4; bC4[e] = idx & 15;
        sBi[e]  = bRow[e] * SB_STR + bC4[e] * 4;
    }

    float acc[2][4][4];
    #pragma unroll
    for (int mt = 0; mt < 2; mt++)
        #pragma unroll
        for (int nt = 0; nt < 4; nt++)
            #pragma unroll
            for (int e = 0; e < 4; e++) acc[mt][nt][e] = 0.f;

    float4 av[4], bv[2];
    #pragma unroll
    for (int e = 0; e < 4; e++)
        av[e] = *(const float4*)&Ap[(row0 + aRow[e]) * 1024 + aC4[e] * 4];
    #pragma unroll
    for (int e = 0; e < 2; e++)
        bv[e] = *(const float4*)&Wm[bRow[e] * 1024 + col0 + bC4[e] * 4];

    for (int t = 0; t < 32; t++) {
        __syncthreads();
        #pragma unroll
        for (int e = 0; e < 4; e++) {
            uint2* d = &sA[sAi[e]];
            d[0] = spl(av[e].x); d[1] = spl(av[e].y);
            d[2] = spl(av[e].z); d[3] = spl(av[e].w);
        }
        #pragma unroll
        for (int e = 0; e < 2; e++) {
            uint2* d = &sB[sBi[e]];
            d[0] = spl(bv[e].x); d[1] = spl(bv[e].y);
            d[2] = spl(bv[e].z); d[3] = spl(bv[e].w);
        }
        __syncthreads();

        if (t < 31) {
            int k0 = (t + 1) * 32;
            #pragma unroll
            for (int e = 0; e < 4; e++)
                av[e] = *(const float4*)&Ap[(row0 + aRow[e]) * 1024 + k0 + aC4[e] * 4];
            #pragma unroll
            for (int e = 0; e < 2; e++)
                bv[e] = *(const float4*)&Wm[(k0 + bRow[e]) * 1024 + col0 + bC4[e] * 4];
        }

        #pragma unroll
        for (int kk = 0; kk < 32; kk += 8) {
            uint2 Afr[2][4];
            #pragma unroll
            for (int mt = 0; mt < 2; mt++) {
                int rb = (wm * 32 + mt * 16 + g) * SA_STR + kk + tg;
                Afr[mt][0] = sA[rb];
                Afr[mt][2] = sA[rb + 4];
                Afr[mt][1] = sA[rb + 8 * SA_STR];
                Afr[mt][3] = sA[rb + 8 * SA_STR + 4];
            }
            #pragma unroll
            for (int nt = 0; nt < 4; nt++) {
                int cb = (kk + tg) * SB_STR + wn * 32 + nt * 8 + g;
                uint2 B0 = sB[cb];
                uint2 B1 = sB[cb + 4 * SB_STR];
                #pragma unroll
                for (int mt = 0; mt < 2; mt++) {
                    float* c = acc[mt][nt];
                    mma8(c, Afr[mt][0].x, Afr[mt][1].x, Afr[mt][2].x, Afr[mt][3].x,
                         B0.x, B1.x);
                    mma8(c, Afr[mt][0].x, Afr[mt][1].x, Afr[mt][2].x, Afr[mt][3].x,
                         B0.y, B1.y);
                    mma8(c, Afr[mt][0].y, Afr[mt][1].y, Afr[mt][2].y, Afr[mt][3].y,
                         B0.x, B1.x);
                }
            }
        }
    }

    if (mode == 1) {
        #pragma unroll
        for (int mt = 0; mt < 2; mt++) {
            int row = row0 + wm * 32 + mt * 16 + g;
            #pragma unroll
            for (int nt = 0; nt < 4; nt++) {
                int col = col0 + wn * 32 + nt * 8 + 2 * tg;
                *(float2*)&Cout[row * 1024 + col] =
                    make_float2(acc[mt][nt][0], acc[mt][nt][1]);
                *(float2*)&Cout[(row + 8) * 1024 + col] =
                    make_float2(acc[mt][nt][2], acc[mt][nt][3]);
            }
        }
    } else {
        int z = blockIdx.z;
        float* dst = (z == 0) ? g_q : (z == 1) ? g_k : g_v;
        int h = blockIdx.x;
        #pragma unroll
        for (int mt = 0; mt < 2; mt++) {
            int row = row0 + wm * 32 + mt * 16 + g;
            int b0r = row >> 9, t0r = row & 511;
            int b1r = (row + 8) >> 9, t1r = (row + 8) & 511;
            #pragma unroll
            for (int nt = 0; nt < 4; nt++) {
                int col = wn * 32 + nt * 8 + 2 * tg;
                *(float2*)&dst[(((b0r << 4) + h) * 512 + t0r) * 64 + col] =
                    make_float2(acc[mt][nt][0], acc[mt][nt][1]);
                *(float2*)&dst[(((b1r << 4) + h) * 512 + t1r) * 64 + col] =
                    make_float2(acc[mt][nt][2], acc[mt][nt][3]);
            }
        }
    }
}

// ---------------- RoPE (in place on g_q, g_k) -------------------------------
__global__ void rope_kernel()
{
    int idx = blockIdx.x * blockDim.x + threadIdx.x;
    if (idx >= BHT * 32) return;
    int tok = idx >> 5;
    int j   = idx & 31;
    int t   = tok & 511;
    float inv = expf(-((float)(2 * j) / 64.0f) * 9.210340371976184f);
    float fr  = (float)t * inv;
    float s, c;
    sincosf(fr, &s, &c);

    float* q = g_q + tok * 64;
    float x1 = q[j], x2 = q[j + 32];
    q[j]      = x1 * c - x2 * s;
    q[j + 32] = x1 * s + x2 * c;

    float* k = g_k + tok * 64;
    x1 = k[j]; x2 = k[j + 32];
    k[j]      = x1 * c - x2 * s;
    k[j + 32] = x1 * s + x2 * c;
}

// ---------------- metric: qm, km, q2, k2, U, Uq (R3 version) ------------------
__global__ void __launch_bounds__(256) metric_kernel(
    const float* __restrict__ Wqm, const float* __restrict__ Wkm,
    const float* __restrict__ Wmetric)
{
    __shared__ float sWqm[64 * 32];
    __shared__ float sWkm[64 * 32];
    __shared__ float sWm [32 * 128];
    int tid = threadIdx.x;
    for (int i = tid; i < 64 * 32; i += 256) { sWqm[i] = Wqm[i]; sWkm[i] = Wkm[i]; }
    for (int i = tid; i < 32 * 128; i += 256) { sWm[i] = Wmetric[i]; }
    __syncthreads();

    const unsigned FULL = 0xffffffffu;
    int w = tid >> 5, lane = tid & 31;
    int tok = blockIdx.x * 8 + w;

    const float* q = g_q + tok * 64;
    const float* k = g_k + tok * 64;
    float a0 = q[lane], a1 = q[lane + 32];
    float b0 = k[lane], b1 = k[lane + 32];

    float accq = 0.f, acck = 0.f;
    #pragma unroll
    for (int d = 0; d < 32; d++) {
        float qd = __shfl_sync(FULL, a0, d);
        float kd = __shfl_sync(FULL, b0, d);
        accq += qd * sWqm[d * 32 + lane];
        acck += kd * sWkm[d * 32 + lane];
    }
    #pragma unroll
    for (int d = 0; d < 32; d++) {
        float qd = __shfl_sync(FULL, a1, d);
        float kd = __shfl_sync(FULL, b1, d);
        accq += qd * sWqm[(d + 32) * 32 + lane];
        acck += kd * sWkm[(d + 32) * 32 + lane];
    }
    float qmv = 1.f / (1.f + expf(-accq));
    float kmv = 1.f / (1.f + expf(-acck));
    g_qm[tok * 32 + lane] = qmv;
    g_km[tok * 32 + lane] = kmv;

    float q2 = qmv * qmv, k2 = kmv * kmv;
    #pragma unroll
    for (int o = 16; o > 0; o >>= 1) {
        q2 += __shfl_xor_sync(FULL, q2, o);
        k2 += __shfl_xor_sync(FULL, k2, o);
    }
    if (lane == 0) { g_q2[tok] = q2; g_k2[tok] = k2; }

    float u0 = 0.f, u1 = 0.f, u2 = 0.f, u3 = 0.f;
    #pragma unroll
    for (int d = 0; d < 32; d++) {
        float qd = __shfl_sync(FULL, qmv, d);
        float4 wv = *(const float4*)&sWm[d * 128 + lane * 4];
        u0 += qd * wv.x; u1 += qd * wv.y; u2 += qd * wv.z; u3 += qd * wv.w;
    }
    *(float4*)&g_U[tok * 128 + lane * 4] = make_float4(u0, u1, u2, u3);

    float p0 = u0 * qmv, p1 = u1 * qmv, p2 = u2 * qmv, p3 = u3 * qmv;
    #pragma unroll
    for (int o = 16; o > 0; o >>= 1) {
        p0 += __shfl_xor_sync(FULL, p0, o);
        p1 += __shfl_xor_sync(FULL, p1, o);
        p2 += __shfl_xor_sync(FULL, p2, o);
        p3 += __shfl_xor_sync(FULL, p3, o);
    }
    if (lane == 0) {
        g_Uq[tok * 4 + 0] = p0; g_Uq[tok * 4 + 1] = p1;
        g_Uq[tok * 4 + 2] = p2; g_Uq[tok * 4 + 3] = p3;
    }
}

// ---------------- attention: R1 dataflow + jc split + __expf ------------------
// block (px, bh): px -> (qt, jc), heavy-first. 256 thr = 128 queries x 2 halves.
// thread (qi, half) in block jc processes tiles jt = 2*jc + half, step 4.
// Partials (unnormalized) -> g_pacc[jc], g_psum[jc]; merged by merge_kernel.
__constant__ int c_qt_map[7] = {3, 3, 2, 2, 1, 1, 0};
__constant__ int c_jc_map[7] = {0, 1, 0, 1, 0, 1, 0};

__global__ void __launch_bounds__(256, 1) attn_kernel(const float* __restrict__ temp_ptr)
{
    extern __shared__ float sm[];
    float* sU  = sm;                        // TQ*USTRIDE
    float* sKm = sU + TQ * USTRIDE;         // 2 * TJ*32
    float* sV  = sKm + 2 * TJ * 32;         // 2 * TJ*64
    float* sK2 = sV + 2 * TJ * 64;          // 2 * TJ

    int qt = c_qt_map[blockIdx.x];
    int jc = c_jc_map[blockIdx.x];
    int bh = blockIdx.y;
    int tid = threadIdx.x;
    int qi = tid & 127;
    int half = tid >> 7;
    int i = qt * TQ + qi;
    int tokBase = bh * Tt;
    int tok = tokBase + i;

    float qm[32];
    #pragma unroll
    for (int d = 0; d < 32; d++) qm[d] = g_qm[tok * 32 + d];
    float Uq0 = g_Uq[tok * 4 + 0], Uq1 = g_Uq[tok * 4 + 1];
    float Uq2 = g_Uq[tok * 4 + 2], Uq3 = g_Uq[tok * 4 + 3];
    float q2  = g_q2[tok];
    float invT = 1.0f / fmaxf(temp_ptr[0], 0.5f);

    for (int idx = tid; idx < TQ * 32; idx += 256) {
        int r = idx >> 5, c4 = idx & 31;
        float4 v = *(const float4*)&g_U[(tokBase + qt * TQ + r) * 128 + c4 * 4];
        *(float4*)&sU[r * USTRIDE + c4 * 4] = v;
    }

    float acc[64];
    #pragma unroll
    for (int c = 0; c < 64; c++) acc[c] = 0.f;
    float lsum = 0.f;

    float* myKm = sKm + half * TJ * 32;
    float* myV  = sV  + half * TJ * 64;
    float* myK2 = sK2 + half * TJ;
    int lt = tid & 127;

    for (int jt = 2 * jc + half; jt <= 2 * qt + 1; jt += 4) {
        int j0 = jt * TJ;
        __syncthreads();
        {
            int tokJ = tokBase + j0;
            #pragma unroll
            for (int p = 0; p < 4; p++) {
                int e = lt + p * 128;
                *(float4*)&myKm[e * 4] = *(const float4*)&g_km[tokJ * 32 + e * 4];
            }
            #pragma unroll
            for (int p = 0; p < 8; p++) {
                int e = lt + p * 128;
                *(float4*)&myV[e * 4] = *(const float4*)&g_v[tokJ * 64 + e * 4];
            }
            if (lt < TJ) myK2[lt] = g_k2[tokJ + lt];
        }
        __syncthreads();

        if (j0 <= i) {
            int jend = min(TJ, i - j0 + 1);
            for (int jj = 0; jj < jend; jj++) {
                const float4* km4 = (const float4*)&myKm[jj * 32];
                float qk = 0.f, u0b = 0.f, u1b = 0.f, u2b = 0.f, u3b = 0.f;
                #pragma unroll
                for (int dd = 0; dd < 8; dd++) {
                    float4 kv = km4[dd];
                    qk += qm[dd*4+0]*kv.x + qm[dd*4+1]*kv.y
                        + qm[dd*4+2]*kv.z + qm[dd*4+3]*kv.w;
                    float4 Ua = *(const float4*)&sU[qi*USTRIDE + (dd*4+0)*4];
                    float4 Ub = *(const float4*)&sU[qi*USTRIDE + (dd*4+1)*4];
                    float4 Uc = *(const float4*)&sU[qi*USTRIDE + (dd*4+2)*4];
                    float4 Ud = *(const float4*)&sU[qi*USTRIDE + (dd*4+3)*4];
                    u0b += kv.x*Ua.x + kv.y*Ub.x + kv.z*Uc.x + kv.w*Ud.x;
                    u1b += kv.x*Ua.y + kv.y*Ub.y + kv.z*Uc.y + kv.w*Ud.y;
                    u2b += kv.x*Ua.z + kv.y*Ub.z + kv.z*Uc.z + kv.w*Ud.z;
                    u3b += kv.x*Ua.w + kv.y*Ub.w + kv.z*Uc.w + kv.w*Ud.w;
                }
                float e0 = Uq0-u0b, e1 = Uq1-u1b, e2 = Uq2-u2b, e3 = Uq3-u3b;
                float dist = q2 + myK2[jj] - 2.f*qk + e0*e0 + e1*e1 + e2*e2 + e3*e3;
                dist = fmaxf(dist, 0.f);
                float p = __expf(-dist * invT);
                lsum += p;
                const float4* v4 = (const float4*)&myV[jj * 64];
                #pragma unroll
                for (int c = 0; c < 16; c++) {
                    float4 vv = v4[c];
                    acc[c*4+0] += p*vv.x; acc[c*4+1] += p*vv.y;
                    acc[c*4+2] += p*vv.z; acc[c*4+3] += p*vv.w;
                }
            }
        }
    }

    __syncthreads();
    if (half == 1) {
        float* mb = sU + qi * 66;
        #pragma unroll
        for (int c = 0; c < 64; c++) mb[c] = acc[c];
        mb[64] = lsum;
    }
    __syncthreads();
    if (half == 0) {
        const float* mb = sU + qi * 66;
        lsum += mb[64];
        g_psum[jc][tok] = lsum;
        float* outp = &g_pacc[jc][(size_t)tok * 64];
        #pragma unroll
        for (int c = 0; c < 64; c += 4) {
            float4 o;
            o.x = acc[c+0] + mb[c+0];
            o.y = acc[c+1] + mb[c+1];
            o.z = acc[c+2] + mb[c+2];
            o.w = acc[c+3] + mb[c+3];
            *(float4*)&outp[c] = o;
        }
    }
}

// ---------------- merge partials -> g_ao -------------------------------------
__global__ void merge_kernel()
{
    int idx = blockIdx.x * 256 + threadIdx.x;    // 262144 items
    int tok = idx >> 4, c4 = idx & 15;
    int i = tok & 511;
    float4 a = *(const float4*)&g_pacc[0][tok * 64 + c4 * 4];
    float s = g_psum[0][tok];
    if (i >= 128) {
        float4 b = *(const float4*)&g_pacc[1][tok * 64 + c4 * 4];
        a.x += b.x; a.y += b.y; a.z += b.z; a.w += b.w;
        s += g_psum[1][tok];
    }
    float inv = 1.f / s;
    int bh = tok >> 9;
    int b = bh >> 4, h = bh & 15;
    float4 o = make_float4(a.x * inv, a.y * inv, a.z * inv, a.w * inv);
    *(float4*)&g_ao[(b * 512 + i) * 1024 + h * 64 + c4 * 4] = o;
}

// ---------------- launch ------------------------------------------------------
extern "C" void kernel_launch(void* const* d_in, const int* in_sizes, int n_in,
                              void* d_out, int out_size)
{
    const float* x    = (const float*)d_in[0];
    const float* Wq   = (const float*)d_in[1];
    const float* Wk   = (const float*)d_in[2];
    const float* Wv   = (const float*)d_in[3];
    const float* Wo   = (const float*)d_in[4];
    const float* Wqm  = (const float*)d_in[5];
    const float* Wkm  = (const float*)d_in[6];
    const float* Wmet = (const float*)d_in[7];
    const float* temp = (const float*)d_in[8];
    float*       out  = (float*)d_out;

    const int attn_smem = (TQ*USTRIDE + 2*TJ*32 + 2*TJ*64 + 2*TJ) * 4;
    cudaFuncSetAttribute(attn_kernel,
                         cudaFuncAttributeMaxDynamicSharedMemorySize, attn_smem);
    cudaFuncSetAttribute(gemm_tc,
                         cudaFuncAttributeMaxDynamicSharedMemorySize, GEMM_SMEM);

    gemm_tc<<<dim3(16, 8, 3), 256, GEMM_SMEM>>>(x, Wq, Wk, Wv, nullptr, 0);
    rope_kernel<<<(BHT * 32) / 256, 256>>>();
    metric_kernel<<<BHT / 8, 256>>>(Wqm, Wkm, Wmet);
    attn_kernel<<<dim3(7, Bb * Hh), 256, attn_smem>>>(temp);
    merge_kernel<<<1024, 256>>>();
    gemm_tc<<<dim3(16, 8, 1), 256, GEMM_SMEM>>>(nullptr, Wo, nullptr, nullptr, out, 1);
}

// round 7
// speedup vs baseline: 1.7950x; 1.2576x over previous
#include <cuda_runtime.h>
#include <math.h>

#define Bb   2
#define Tt   512
#define Hh   16
#define BHT  16384

// ---------------- scratch ----------------------------------------------------
__device__ float g_q [BHT*64];
__device__ float g_k [BHT*64];
__device__ float g_v [BHT*64];
__device__ float g_km[BHT*32];
__device__ float g_k2[BHT];
__device__ float g_U [BHT*128];
__device__ float g_m [BHT*32];
__device__ float g_c [BHT];
__device__ float g_pacc[2][BHT*64];
__device__ float g_psum[2][BHT];
__device__ float g_ao[Bb*Tt*1024];

// ---------------- tf32 helpers ------------------------------------------------
__device__ __forceinline__ unsigned tf32of(float x) {
    unsigned r; asm("cvt.rna.tf32.f32 %0,%1;" : "=r"(r) : "f"(x)); return r;
}
__device__ __forceinline__ uint2 spl(float x) {
    unsigned h = tf32of(x);
    unsigned l = tf32of(x - __uint_as_float(h));
    return make_uint2(h, l);
}
__device__ __forceinline__ void mma8(float* c,
    unsigned a0, unsigned a1, unsigned a2, unsigned a3,
    unsigned b0, unsigned b1)
{
    asm volatile(
        "mma.sync.aligned.m16n8k8.row.col.f32.tf32.tf32.f32 "
        "{%0,%1,%2,%3},{%4,%5,%6,%7},{%8,%9},{%0,%1,%2,%3};"
        : "+f"(c[0]), "+f"(c[1]), "+f"(c[2]), "+f"(c[3])
        : "r"(a0), "r"(a1), "r"(a2), "r"(a3), "r"(b0), "r"(b1));
}

// ---------------- GEMM via tensor cores (3xTF32) — unchanged from R3 ----------
#define SA_STR 36
#define SB_STR 68
#define GEMM_SMEM ((128*SA_STR + 32*SB_STR) * 8)

__global__ void __launch_bounds__(256) gemm_tc(
    const float* __restrict__ A,
    const float* __restrict__ W0, const float* __restrict__ W1,
    const float* __restrict__ W2,
    float* __restrict__ Cout, int mode)
{
    extern __shared__ uint2 sm2[];
    uint2* sA = sm2;
    uint2* sB = sm2 + 128 * SA_STR;

    const float* Ap = (mode == 0) ? A : g_ao;
    const float* Wm = (mode == 0)
        ? (blockIdx.z == 0 ? W0 : (blockIdx.z == 1 ? W1 : W2))
        : W0;

    int tid  = threadIdx.x;
    int lane = tid & 31;
    int wid  = tid >> 5;
    int wm   = wid & 3;
    int wn   = wid >> 2;
    int g    = lane >> 2;
    int tg   = lane & 3;
    int row0 = blockIdx.y * 128;
    int col0 = blockIdx.x * 64;

    int aRow[4], aC4[4], sAi[4];
    #pragma unroll
    for (int e = 0; e < 4; e++) {
        int idx = tid + e * 256;
        aRow[e] = idx >> 3; aC4[e] = idx & 7;
        sAi[e]  = aRow[e] * SA_STR + aC4[e] * 4;
    }
    int bRow[2], bC4[2], sBi[2];
    #pragma unroll
    for (int e = 0; e < 2; e++) {
        int idx = tid + e * 256;
        bRow[e] = idx >> 4; bC4[e] = idx & 15;
        sBi[e]  = bRow[e] * SB_STR + bC4[e] * 4;
    }

    float acc[2][4][4];
    #pragma unroll
    for (int mt = 0; mt < 2; mt++)
        #pragma unroll
        for (int nt = 0; nt < 4; nt++)
            #pragma unroll
            for (int e = 0; e < 4; e++) acc[mt][nt][e] = 0.f;

    float4 av[4], bv[2];
    #pragma unroll
    for (int e = 0; e < 4; e++)
        av[e] = *(const float4*)&Ap[(row0 + aRow[e]) * 1024 + aC4[e] * 4];
    #pragma unroll
    for (int e = 0; e < 2; e++)
        bv[e] = *(const float4*)&Wm[bRow[e] * 1024 + col0 + bC4[e] * 4];

    for (int t = 0; t < 32; t++) {
        __syncthreads();
        #pragma unroll
        for (int e = 0; e < 4; e++) {
            uint2* d = &sA[sAi[e]];
            d[0] = spl(av[e].x); d[1] = spl(av[e].y);
            d[2] = spl(av[e].z); d[3] = spl(av[e].w);
        }
        #pragma unroll
        for (int e = 0; e < 2; e++) {
            uint2* d = &sB[sBi[e]];
            d[0] = spl(bv[e].x); d[1] = spl(bv[e].y);
            d[2] = spl(bv[e].z); d[3] = spl(bv[e].w);
        }
        __syncthreads();

        if (t < 31) {
            int k0 = (t + 1) * 32;
            #pragma unroll
            for (int e = 0; e < 4; e++)
                av[e] = *(const float4*)&Ap[(row0 + aRow[e]) * 1024 + k0 + aC4[e] * 4];
            #pragma unroll
            for (int e = 0; e < 2; e++)
                bv[e] = *(const float4*)&Wm[(k0 + bRow[e]) * 1024 + col0 + bC4[e] * 4];
        }

        #pragma unroll
        for (int kk = 0; kk < 32; kk += 8) {
            uint2 Afr[2][4];
            #pragma unroll
            for (int mt = 0; mt < 2; mt++) {
                int rb = (wm * 32 + mt * 16 + g) * SA_STR + kk + tg;
                Afr[mt][0] = sA[rb];
                Afr[mt][2] = sA[rb + 4];
                Afr[mt][1] = sA[rb + 8 * SA_STR];
                Afr[mt][3] = sA[rb + 8 * SA_STR + 4];
            }
            #pragma unroll
            for (int nt = 0; nt < 4; nt++) {
                int cb = (kk + tg) * SB_STR + wn * 32 + nt * 8 + g;
                uint2 B0 = sB[cb];
                uint2 B1 = sB[cb + 4 * SB_STR];
                #pragma unroll
                for (int mt = 0; mt < 2; mt++) {
                    float* c = acc[mt][nt];
                    mma8(c, Afr[mt][0].x, Afr[mt][1].x, Afr[mt][2].x, Afr[mt][3].x,
                         B0.x, B1.x);
                    mma8(c, Afr[mt][0].x, Afr[mt][1].x, Afr[mt][2].x, Afr[mt][3].x,
                         B0.y, B1.y);
                    mma8(c, Afr[mt][0].y, Afr[mt][1].y, Afr[mt][2].y, Afr[mt][3].y,
                         B0.x, B1.x);
                }
            }
        }
    }

    if (mode == 1) {
        #pragma unroll
        for (int mt = 0; mt < 2; mt++) {
            int row = row0 + wm * 32 + mt * 16 + g;
            #pragma unroll
            for (int nt = 0; nt < 4; nt++) {
                int col = col0 + wn * 32 + nt * 8 + 2 * tg;
                *(float2*)&Cout[row * 1024 + col] =
                    make_float2(acc[mt][nt][0], acc[mt][nt][1]);
                *(float2*)&Cout[(row + 8) * 1024 + col] =
                    make_float2(acc[mt][nt][2], acc[mt][nt][3]);
            }
        }
    } else {
        int z = blockIdx.z;
        float* dst = (z == 0) ? g_q : (z == 1) ? g_k : g_v;
        int h = blockIdx.x;
        #pragma unroll
        for (int mt = 0; mt < 2; mt++) {
            int row = row0 + wm * 32 + mt * 16 + g;
            int b0r = row >> 9, t0r = row & 511;
            int b1r = (row + 8) >> 9, t1r = (row + 8) & 511;
            #pragma unroll
            for (int nt = 0; nt < 4; nt++) {
                int col = wn * 32 + nt * 8 + 2 * tg;
                *(float2*)&dst[(((b0r << 4) + h) * 512 + t0r) * 64 + col] =
                    make_float2(acc[mt][nt][0], acc[mt][nt][1]);
                *(float2*)&dst[(((b1r << 4) + h) * 512 + t1r) * 64 + col] =
                    make_float2(acc[mt][nt][2], acc[mt][nt][3]);
            }
        }
    }
}

// ---------------- RoPE (in place on g_q, g_k) -------------------------------
__global__ void rope_kernel()
{
    int idx = blockIdx.x * blockDim.x + threadIdx.x;
    if (idx >= BHT * 32) return;
    int tok = idx >> 5;
    int j   = idx & 31;
    int t   = tok & 511;
    float inv = expf(-((float)(2 * j) / 64.0f) * 9.210340371976184f);
    float fr  = (float)t * inv;
    float s, c;
    sincosf(fr, &s, &c);

    float* q = g_q + tok * 64;
    float x1 = q[j], x2 = q[j + 32];
    q[j]      = x1 * c - x2 * s;
    q[j + 32] = x1 * s + x2 * c;

    float* k = g_k + tok * 64;
    x1 = k[j]; x2 = k[j + 32];
    k[j]      = x1 * c - x2 * s;
    k[j + 32] = x1 * s + x2 * c;
}

// ---------------- metric (R4): km, k2, U, m = qm+w, c = q2+|Uq|^2 ------------
__global__ void __launch_bounds__(256) metric_kernel(
    const float* __restrict__ Wqm, const float* __restrict__ Wkm,
    const float* __restrict__ Wmetric)
{
    __shared__ float sWqm[64 * 32];
    __shared__ float sWkm[64 * 32];
    __shared__ float sWm [32 * 128];
    int tid = threadIdx.x;
    for (int i = tid; i < 64 * 32; i += 256) { sWqm[i] = Wqm[i]; sWkm[i] = Wkm[i]; }
    for (int i = tid; i < 32 * 128; i += 256) { sWm[i] = Wmetric[i]; }
    __syncthreads();

    const unsigned FULL = 0xffffffffu;
    int w = tid >> 5, lane = tid & 31;
    int tok = blockIdx.x * 8 + w;

    const float* q = g_q + tok * 64;
    const float* k = g_k + tok * 64;
    float a0 = q[lane], a1 = q[lane + 32];
    float b0 = k[lane], b1 = k[lane + 32];

    float accq = 0.f, acck = 0.f;
    #pragma unroll
    for (int d = 0; d < 32; d++) {
        float qd = __shfl_sync(FULL, a0, d);
        float kd = __shfl_sync(FULL, b0, d);
        accq += qd * sWqm[d * 32 + lane];
        acck += kd * sWkm[d * 32 + lane];
    }
    #pragma unroll
    for (int d = 0; d < 32; d++) {
        float qd = __shfl_sync(FULL, a1, d);
        float kd = __shfl_sync(FULL, b1, d);
        accq += qd * sWqm[(d + 32) * 32 + lane];
        acck += kd * sWkm[(d + 32) * 32 + lane];
    }
    float qmv = 1.f / (1.f + expf(-accq));
    float kmv = 1.f / (1.f + expf(-acck));
    g_km[tok * 32 + lane] = kmv;

    float q2 = qmv * qmv, k2 = kmv * kmv;
    #pragma unroll
    for (int o = 16; o > 0; o >>= 1) {
        q2 += __shfl_xor_sync(FULL, q2, o);
        k2 += __shfl_xor_sync(FULL, k2, o);
    }
    if (lane == 0) g_k2[tok] = k2;

    float u0 = 0.f, u1 = 0.f, u2 = 0.f, u3 = 0.f;
    #pragma unroll
    for (int d = 0; d < 32; d++) {
        float qd = __shfl_sync(FULL, qmv, d);
        float4 wv = *(const float4*)&sWm[d * 128 + lane * 4];
        u0 += qd * wv.x; u1 += qd * wv.y; u2 += qd * wv.z; u3 += qd * wv.w;
    }
    *(float4*)&g_U[tok * 128 + lane * 4] = make_float4(u0, u1, u2, u3);

    float p0 = u0 * qmv, p1 = u1 * qmv, p2 = u2 * qmv, p3 = u3 * qmv;
    #pragma unroll
    for (int o = 16; o > 0; o >>= 1) {
        p0 += __shfl_xor_sync(FULL, p0, o);
        p1 += __shfl_xor_sync(FULL, p1, o);
        p2 += __shfl_xor_sync(FULL, p2, o);
        p3 += __shfl_xor_sync(FULL, p3, o);
    }
    float wd = p0 * u0 + p1 * u1 + p2 * u2 + p3 * u3;
    g_m[tok * 32 + lane] = qmv + wd;
    if (lane == 0)
        g_c[tok] = q2 + p0 * p0 + p1 * p1 + p2 * p2 + p3 * p3;
}

// ---------------- attention via MMA -------------------------------------------
// dist(i,j) = c_i + k2_j - 2 m_i.km_j + sum_r (U_i.km_j)^2 ; p = exp(-dist/T)
// Block (px, bh): px -> (qt, jc); 128 queries, jtiles of 64 with jt%2==jc.
// qk: 3xtf32. Uk_r: single tf32. PV: 3-pass (P,V hi/lo split).
// sKm is [d=32][j=64] transposed, stride KM_STR (>=64 — R6 bug was 33).
#define KM_STR 66
#define V_STR  66
#define P_STR  66
#define ATTN_SMEM ((32*KM_STR + 64*V_STR + 128*P_STR) * 8 + 64 * 4)

__global__ void __launch_bounds__(256) attn_mma(const float* __restrict__ temp_ptr)
{
    extern __shared__ uint2 smem[];
    uint2* sKm = smem;                         // [32][KM_STR] km transposed, split
    uint2* sV  = sKm + 32 * KM_STR;            // [64][V_STR]
    uint2* sP  = sV + 64 * V_STR;              // [128][P_STR]
    float* sK2 = (float*)(sP + 128 * P_STR);   // [64]

    int qt = 3 - (int)(blockIdx.x >> 1);       // heavy first
    int jc = blockIdx.x & 1;
    int bh = blockIdx.y;
    int tok0 = bh * 512 + qt * 128;

    int tid  = threadIdx.x;
    int lane = tid & 31;
    int wid  = tid >> 5;
    int g    = lane >> 2;
    int tg   = lane & 3;
    int r0w  = wid * 16;                       // warp's query-row base (0..112)

    float invT = 1.0f / fmaxf(temp_ptr[0], 0.5f);

    int rA = tok0 + r0w + g;                   // token of row g
    int rB = rA + 8;
    int iRelA = qt * 128 + r0w + g;            // within-sequence index
    int iRelB = iRelA + 8;

    // ---- A-side fragments in registers (once per block) ----
    uint2 mm[4][4];                            // m hi/lo frags [kstep][slot]
    unsigned uf[4][4][4];                      // U frags [r][kstep][slot]
    #pragma unroll
    for (int kk = 0; kk < 4; kk++) {
        int d0 = kk * 8 + tg;
        mm[kk][0] = spl(g_m[rA * 32 + d0]);
        mm[kk][1] = spl(g_m[rB * 32 + d0]);
        mm[kk][2] = spl(g_m[rA * 32 + d0 + 4]);
        mm[kk][3] = spl(g_m[rB * 32 + d0 + 4]);
        float4 uA0 = *(const float4*)&g_U[rA * 128 + d0 * 4];
        float4 uB0 = *(const float4*)&g_U[rB * 128 + d0 * 4];
        float4 uA4 = *(const float4*)&g_U[rA * 128 + (d0 + 4) * 4];
        float4 uB4 = *(const float4*)&g_U[rB * 128 + (d0 + 4) * 4];
        #pragma unroll
        for (int r = 0; r < 4; r++) {
            uf[r][kk][0] = tf32of(((const float*)&uA0)[r]);
            uf[r][kk][1] = tf32of(((const float*)&uB0)[r]);
            uf[r][kk][2] = tf32of(((const float*)&uA4)[r]);
            uf[r][kk][3] = tf32of(((const float*)&uB4)[r]);
        }
    }
    float ci0 = g_c[rA], ci1 = g_c[rB];

    float cpv[8][4];
    #pragma unroll
    for (int nt = 0; nt < 8; nt++)
        #pragma unroll
        for (int e = 0; e < 4; e++) cpv[nt][e] = 0.f;
    float runs0 = 0.f, runs1 = 0.f;

    // staging identities
    int sj   = tid >> 2;                       // 0..63
    int sgrp = tid & 3;

    for (int jt = jc; jt <= 2 * qt + 1; jt += 2) {
        int j0 = jt * 64;
        int tokJ = bh * 512 + j0;
        __syncthreads();
        // ---- stage km (transposed, split), V (split), k2 ----
        {
            float4 k0 = *(const float4*)&g_km[(tokJ + sj) * 32 + sgrp * 8];
            float4 k1 = *(const float4*)&g_km[(tokJ + sj) * 32 + sgrp * 8 + 4];
            #pragma unroll
            for (int t = 0; t < 4; t++)
                sKm[(sgrp * 8 + t) * KM_STR + sj] = spl(((const float*)&k0)[t]);
            #pragma unroll
            for (int t = 0; t < 4; t++)
                sKm[(sgrp * 8 + 4 + t) * KM_STR + sj] = spl(((const float*)&k1)[t]);
            #pragma unroll
            for (int q4 = 0; q4 < 4; q4++) {
                float4 vv = *(const float4*)&g_v[(tokJ + sj) * 64 + sgrp * 16 + q4 * 4];
                #pragma unroll
                for (int t = 0; t < 4; t++)
                    sV[sj * V_STR + sgrp * 16 + q4 * 4 + t] = spl(((const float*)&vv)[t]);
            }
            if (tid < 64) sK2[tid] = g_k2[tokJ + tid];
        }
        __syncthreads();

        // ---- scores: 8 n-tiles of 8 cols ----
        #pragma unroll
        for (int nt = 0; nt < 8; nt++) {
            float cqk[4] = {0.f, 0.f, 0.f, 0.f};
            float cu0[4] = {0.f, 0.f, 0.f, 0.f};
            float cu1[4] = {0.f, 0.f, 0.f, 0.f};
            float cu2[4] = {0.f, 0.f, 0.f, 0.f};
            float cu3[4] = {0.f, 0.f, 0.f, 0.f};
            #pragma unroll
            for (int kk = 0; kk < 4; kk++) {
                uint2 b0 = sKm[(kk * 8 + tg) * KM_STR + nt * 8 + g];
                uint2 b1 = sKm[(kk * 8 + tg + 4) * KM_STR + nt * 8 + g];
                mma8(cqk, mm[kk][0].x, mm[kk][1].x, mm[kk][2].x, mm[kk][3].x, b0.x, b1.x);
                mma8(cqk, mm[kk][0].x, mm[kk][1].x, mm[kk][2].x, mm[kk][3].x, b0.y, b1.y);
                mma8(cqk, mm[kk][0].y, mm[kk][1].y, mm[kk][2].y, mm[kk][3].y, b0.x, b1.x);
                mma8(cu0, uf[0][kk][0], uf[0][kk][1], uf[0][kk][2], uf[0][kk][3], b0.x, b1.x);
                mma8(cu1, uf[1][kk][0], uf[1][kk][1], uf[1][kk][2], uf[1][kk][3], b0.x, b1.x);
                mma8(cu2, uf[2][kk][0], uf[2][kk][1], uf[2][kk][2], uf[2][kk][3], b0.x, b1.x);
                mma8(cu3, uf[3][kk][0], uf[3][kk][1], uf[3][kk][2], uf[3][kk][3], b0.x, b1.x);
            }
            // epilogue for this n-tile
            int colA = nt * 8 + 2 * tg;
            float2 k2p = *(const float2*)&sK2[colA];
            int jRelA = j0 + colA, jRelB = jRelA + 1;
            float p[4];
            #pragma unroll
            for (int e = 0; e < 4; e++) {
                float cival = (e < 2) ? ci0 : ci1;
                float k2v   = (e & 1) ? k2p.y : k2p.x;
                float dist = cival + k2v - 2.f * cqk[e]
                           + cu0[e] * cu0[e] + cu1[e] * cu1[e]
                           + cu2[e] * cu2[e] + cu3[e] * cu3[e];
                p[e] = __expf(-fmaxf(dist, 0.f) * invT);
            }
            if (jRelA > iRelA) p[0] = 0.f;
            if (jRelB > iRelA) p[1] = 0.f;
            if (jRelA > iRelB) p[2] = 0.f;
            if (jRelB > iRelB) p[3] = 0.f;
            runs0 += p[0] + p[1];
            runs1 += p[2] + p[3];
            uint2 s0 = spl(p[0]), s1 = spl(p[1]);
            uint2 s2 = spl(p[2]), s3 = spl(p[3]);
            *(uint4*)&sP[(r0w + g) * P_STR + colA]     = make_uint4(s0.x, s0.y, s1.x, s1.y);
            *(uint4*)&sP[(r0w + g + 8) * P_STR + colA] = make_uint4(s2.x, s2.y, s3.x, s3.y);
        }
        __syncwarp();

        // ---- PV: cpv += P @ V (3-pass split) ----
        #pragma unroll
        for (int kk = 0; kk < 8; kk++) {
            uint2 A0 = sP[(r0w + g) * P_STR + kk * 8 + tg];
            uint2 A1 = sP[(r0w + g + 8) * P_STR + kk * 8 + tg];
            uint2 A2 = sP[(r0w + g) * P_STR + kk * 8 + tg + 4];
            uint2 A3 = sP[(r0w + g + 8) * P_STR + kk * 8 + tg + 4];
            #pragma unroll
            for (int nt = 0; nt < 8; nt++) {
                uint2 b0 = sV[(kk * 8 + tg) * V_STR + nt * 8 + g];
                uint2 b1 = sV[(kk * 8 + tg + 4) * V_STR + nt * 8 + g];
                mma8(cpv[nt], A0.x, A1.x, A2.x, A3.x, b0.x, b1.x);
                mma8(cpv[nt], A0.x, A1.x, A2.x, A3.x, b0.y, b1.y);
                mma8(cpv[nt], A0.y, A1.y, A2.y, A3.y, b0.x, b1.x);
            }
        }
    }

    // ---- write partials ----
    const unsigned FULL = 0xffffffffu;
    float s0 = runs0, s1 = runs1;
    s0 += __shfl_xor_sync(FULL, s0, 1); s0 += __shfl_xor_sync(FULL, s0, 2);
    s1 += __shfl_xor_sync(FULL, s1, 1); s1 += __shfl_xor_sync(FULL, s1, 2);
    if (tg == 0) {
        g_psum[jc][rA] = s0;
        g_psum[jc][rB] = s1;
    }
    #pragma unroll
    for (int nt = 0; nt < 8; nt++) {
        int col = nt * 8 + 2 * tg;
        *(float2*)&g_pacc[jc][(size_t)rA * 64 + col] = make_float2(cpv[nt][0], cpv[nt][1]);
        *(float2*)&g_pacc[jc][(size_t)rB * 64 + col] = make_float2(cpv[nt][2], cpv[nt][3]);
    }
}

// ---------------- merge partials -> g_ao -------------------------------------
__global__ void merge_kernel()
{
    int idx = blockIdx.x * 256 + threadIdx.x;    // 262144 items
    int tok = idx >> 4, c4 = idx & 15;
    int i = tok & 511;
    float4 a = *(const float4*)&g_pacc[0][tok * 64 + c4 * 4];
    float s = g_psum[0][tok];
    int iq = i & 127;                            // index within q-tile
    if (iq >= 64 || i >= 128) {
        float4 b = *(const float4*)&g_pacc[1][tok * 64 + c4 * 4];
        a.x += b.x; a.y += b.y; a.z += b.z; a.w += b.w;
        s += g_psum[1][tok];
    }
    float inv = 1.f / s;
    int bh = tok >> 9;
    int b = bh >> 4, h = bh & 15;
    float4 o = make_float4(a.x * inv, a.y * inv, a.z * inv, a.w * inv);
    *(float4*)&g_ao[(b * 512 + i) * 1024 + h * 64 + c4 * 4] = o;
}

// ---------------- launch ------------------------------------------------------
extern "C" void kernel_launch(void* const* d_in, const int* in_sizes, int n_in,
                              void* d_out, int out_size)
{
    const float* x    = (const float*)d_in[0];
    const float* Wq   = (const float*)d_in[1];
    const float* Wk   = (const float*)d_in[2];
    const float* Wv   = (const float*)d_in[3];
    const float* Wo   = (const float*)d_in[4];
    const float* Wqm  = (const float*)d_in[5];
    const float* Wkm  = (const float*)d_in[6];
    const float* Wmet = (const float*)d_in[7];
    const float* temp = (const float*)d_in[8];
    float*       out  = (float*)d_out;

    cudaFuncSetAttribute(gemm_tc,
                         cudaFuncAttributeMaxDynamicSharedMemorySize, GEMM_SMEM);
    cudaFuncSetAttribute(attn_mma,
                         cudaFuncAttributeMaxDynamicSharedMemorySize, ATTN_SMEM);

    gemm_tc<<<dim3(16, 8, 3), 256, GEMM_SMEM>>>(x, Wq, Wk, Wv, nullptr, 0);
    rope_kernel<<<(BHT * 32) / 256, 256>>>();
    metric_kernel<<<BHT / 8, 256>>>(Wqm, Wkm, Wmet);
    attn_mma<<<dim3(8, Bb * Hh), 256, ATTN_SMEM>>>(temp);
    merge_kernel<<<1024, 256>>>();
    gemm_tc<<<dim3(16, 8, 1), 256, GEMM_SMEM>>>(nullptr, Wo, nullptr, nullptr, out, 1);
}